// round 3
// baseline (speedup 1.0000x reference)
#include <cuda_runtime.h>
#include <cuda_bf16.h>
#include <math.h>

// Problem shape (fixed): output [B=2, C=8, H=128, W=128, D=128] fp32.
// Slice (one (b,c)) = 128^3 = 2,097,152 elems = 524,288 float4.
// Grid: 16 slices * 64 blocks = 1024 blocks, 256 threads (single wave on 148 SMs).
// Each block reduces 8192 float4 (32 KB), then the LAST block to finish
// performs the final 1024-partial reduction + relation loss (threadfence pattern).

#define NSLICE       16
#define BLK_PER_SL   64
#define NBLOCKS      (NSLICE * BLK_PER_SL)   // 1024
#define THREADS      256
#define F4_PER_BLK   8192
#define SLICE_F4     524288

// per-block partials: [slice][blk] -> float4 {s, sum_t*h, sum_t*w, sum_t*d}
__device__ float4 g_partial[NBLOCKS];
__device__ unsigned int g_count = 0;

// Relations table: (i, j, gy, gx, gz)
__device__ __constant__ int   c_ri[8] = {0, 1, 2, 3, 4, 5, 6, 0};
__device__ __constant__ int   c_rj[8] = {1, 2, 3, 4, 5, 6, 7, 7};
__device__ __constant__ float c_gy[8] = { 0.1f, 0.0f, -0.1f, 0.0f,  0.05f, 0.0f,  0.1f, -0.05f};
__device__ __constant__ float c_gx[8] = { 0.0f, 0.1f,  0.05f, 0.0f, -0.05f, 0.1f, 0.0f,  0.05f};
__device__ __constant__ float c_gz[8] = { 0.05f, 0.0f, 0.0f,  0.1f,  0.0f, -0.1f, 0.0f,  0.05f};

__global__ __launch_bounds__(THREADS) void fused_kernel(const float* __restrict__ in,
                                                        float* __restrict__ out) {
    const int bc  = blockIdx.x >> 6;        // slice 0..15
    const int blk = blockIdx.x & 63;        // block within slice
    const int tid = threadIdx.x;

    const float4* __restrict__ p =
        reinterpret_cast<const float4*>(in) + (size_t)bc * SLICE_F4 + (size_t)blk * F4_PER_BLK;

    float s = 0.f, sy = 0.f, sx = 0.f, sz = 0.f;

#pragma unroll 8
    for (int i = tid; i < F4_PER_BLK; i += THREADS) {
        float4 v = __ldcs(p + i);            // streaming: read-once data
        int e = (blk * F4_PER_BLK + i) << 2; // element index within slice (lane .x)
        float t0 = v.x > 0.5f ? v.x : 0.f;
        float t1 = v.y > 0.5f ? v.y : 0.f;
        float t2 = v.z > 0.5f ? v.z : 0.f;
        float t3 = v.w > 0.5f ? v.w : 0.f;
        float tsum = (t0 + t1) + (t2 + t3);

        float fh = (float)(e >> 14);          // h
        float fw = (float)((e >> 7) & 127);   // w
        float fd = (float)(e & 127);          // d of lane .x (lanes: d..d+3)

        s += tsum;
        sy = fmaf(tsum, fh, sy);
        sx = fmaf(tsum, fw, sx);
        sz = fmaf(tsum, fd, sz) + (t1 + 2.f * t2 + 3.f * t3);
    }

    // warp reduction
    const unsigned FULL = 0xFFFFFFFFu;
#pragma unroll
    for (int off = 16; off > 0; off >>= 1) {
        s  += __shfl_down_sync(FULL, s,  off);
        sy += __shfl_down_sync(FULL, sy, off);
        sx += __shfl_down_sync(FULL, sx, off);
        sz += __shfl_down_sync(FULL, sz, off);
    }

    __shared__ float4 warp_acc[THREADS / 32];
    int lane = tid & 31;
    int wid  = tid >> 5;
    if (lane == 0) warp_acc[wid] = make_float4(s, sy, sx, sz);
    __syncthreads();

    if (wid == 0) {
        float4 a = (lane < THREADS / 32) ? warp_acc[lane] : make_float4(0.f, 0.f, 0.f, 0.f);
#pragma unroll
        for (int off = 4; off > 0; off >>= 1) {
            a.x += __shfl_down_sync(FULL, a.x, off);
            a.y += __shfl_down_sync(FULL, a.y, off);
            a.z += __shfl_down_sync(FULL, a.z, off);
            a.w += __shfl_down_sync(FULL, a.w, off);
        }
        if (lane == 0) g_partial[blockIdx.x] = a;
    }

    // ---- last-block finalize (threadfence reduction pattern) ----
    __threadfence();
    __shared__ bool is_last;
    if (tid == 0) {
        unsigned old = atomicAdd(&g_count, 1u);
        is_last = (old == (unsigned)(NBLOCKS - 1));
        if (is_last) g_count = 0;            // reset for next (graph-replayed) launch
    }
    __syncthreads();
    if (!is_last) return;
    __threadfence();                         // acquire: order our reads after the atomic

    __shared__ float4 sh[NBLOCKS];           // 16 KB
    __shared__ float  cent[NSLICE][3];
#pragma unroll
    for (int k = tid; k < NBLOCKS; k += THREADS) {
        const float4* gp = &g_partial[k];
        float4 a;
        a.x = __ldcg(&gp->x); a.y = __ldcg(&gp->y);
        a.z = __ldcg(&gp->z); a.w = __ldcg(&gp->w);
        sh[k] = a;
    }
    __syncthreads();

    if (tid < NSLICE) {
        float ss = 0.f, ssy = 0.f, ssx = 0.f, ssz = 0.f;
#pragma unroll
        for (int k = 0; k < BLK_PER_SL; k++) {
            float4 a = sh[tid * BLK_PER_SL + k];
            ss += a.x; ssy += a.y; ssx += a.z; ssz += a.w;
        }
        const float inv128 = 1.0f / 128.0f;
        float inv_s = 1.0f / ss;             // inf if ss==0; guarded below
        cent[tid][0] = ssy * inv_s * inv128;
        cent[tid][1] = ssx * inv_s * inv128;
        cent[tid][2] = ssz * inv_s * inv128;
    }
    __syncthreads();

    if (tid == 0) {
        float loss = 0.f;
#pragma unroll
        for (int r = 0; r < 8; r++) {
            int i = c_ri[r], j = c_rj[r];
            float acc = 0.f;
#pragma unroll
            for (int b = 0; b < 2; b++) {
                float dy = cent[b * 8 + i][0] - cent[b * 8 + j][0] - c_gy[r];
                float dx = cent[b * 8 + i][1] - cent[b * 8 + j][1] - c_gx[r];
                float dz = cent[b * 8 + i][2] - cent[b * 8 + j][2] - c_gz[r];
                if (!isfinite(dy)) dy = 0.f;
                if (!isfinite(dx)) dx = 0.f;
                if (!isfinite(dz)) dz = 0.f;
                acc += dy * dy + dx * dx + dz * dz;
            }
            loss += 0.5f * acc;              // mean over batch (B=2)
        }
        out[0] = loss;
    }
}

extern "C" void kernel_launch(void* const* d_in, const int* in_sizes, int n_in,
                              void* d_out, int out_size) {
    const float* in = (const float*)d_in[0];
    float* out = (float*)d_out;
    (void)in_sizes; (void)n_in; (void)out_size;

    fused_kernel<<<NBLOCKS, THREADS>>>(in, out);
}

// round 5
// speedup vs baseline: 1.1525x; 1.1525x over previous
#include <cuda_runtime.h>
#include <cuda_bf16.h>
#include <math.h>

// Shape (fixed): output [B=2, C=8, H=128, W=128, D=128] fp32.
// Slice = 128^3 = 2,097,152 elems = 524,288 float4.
// Grid: 1024 blocks x 256 threads, one wave (needs <=36 regs for 7 CTA/SM).
// Block = 8192 float4, processed as 8 outer x 4 front-batched float4/thread.
//
// Index decomposition for slice-local f4 = X*256 + tid, X = lblk*32 + b*4 + u:
//   d-weight: (tid&31)*4            (constant per thread)
//   w       : 32*(b&3) + 8u + (tid>>5)   (immediate + per-thread constant)
//   h       : 2*lblk + (b>>2)            (constant per outer iteration)

#define NSLICE       16
#define BLK_PER_SL   64
#define NBLOCKS      (NSLICE * BLK_PER_SL)   // 1024
#define THREADS      256
#define F4_PER_BLK   8192
#define SLICE_F4     524288

__device__ float4 g_partial[NBLOCKS];
__device__ unsigned int g_count = 0;

__device__ __constant__ int   c_ri[8] = {0, 1, 2, 3, 4, 5, 6, 0};
__device__ __constant__ int   c_rj[8] = {1, 2, 3, 4, 5, 6, 7, 7};
__device__ __constant__ float c_gy[8] = { 0.1f, 0.0f, -0.1f, 0.0f,  0.05f, 0.0f,  0.1f, -0.05f};
__device__ __constant__ float c_gx[8] = { 0.0f, 0.1f,  0.05f, 0.0f, -0.05f, 0.1f, 0.0f,  0.05f};
__device__ __constant__ float c_gz[8] = { 0.05f, 0.0f, 0.0f,  0.1f,  0.0f, -0.1f, 0.0f,  0.05f};

__global__ __launch_bounds__(THREADS, 7) void fused_kernel(const float* __restrict__ in,
                                                           float* __restrict__ out) {
    const int bc   = blockIdx.x >> 6;        // slice 0..15
    const int lblk = blockIdx.x & 63;        // block within slice
    const int tid  = threadIdx.x;

    const float4* __restrict__ p =
        reinterpret_cast<const float4*>(in) + (size_t)bc * SLICE_F4 + (size_t)lblk * F4_PER_BLK;

    float s_lo = 0.f, s_hi = 0.f, sxl = 0.f, szf = 0.f;

#pragma unroll
    for (int b = 0; b < 8; b++) {
        // front-batched loads: 4 independent LDG.128 issued before any use
        float4 v0 = p[b * 1024 + 0 * 256 + tid];
        float4 v1 = p[b * 1024 + 1 * 256 + tid];
        float4 v2 = p[b * 1024 + 2 * 256 + tid];
        float4 v3 = p[b * 1024 + 3 * 256 + tid];

        float bsum = 0.f;
#pragma unroll
        for (int u = 0; u < 4; u++) {
            float4 v = (u == 0) ? v0 : (u == 1) ? v1 : (u == 2) ? v2 : v3;
            float t0 = v.x > 0.5f ? v.x : 0.f;
            float t1 = v.y > 0.5f ? v.y : 0.f;
            float t2 = v.z > 0.5f ? v.z : 0.f;
            float t3 = v.w > 0.5f ? v.w : 0.f;
            float tsum = (t0 + t1) + (t2 + t3);

            bsum += tsum;
            // w-base = 32*(b&3) + 8u  -> compile-time immediate FFMA
            sxl = fmaf(tsum, (float)(32 * (b & 3) + 8 * u), sxl);
            // fractional d within the float4: t1 + 2*t2 + 3*t3
            szf += t0 * 0.f + t1;                 // (t0*0 folded away)
            szf = fmaf(2.f, t2, szf);
            szf = fmaf(3.f, t3, szf);
        }
        if (b < 4) s_lo += bsum; else s_hi += bsum;   // h = 2*lblk + (b>>2)
    }

    float s  = s_lo + s_hi;
    float fd = (float)((tid & 31) << 2);
    float wt = (float)(tid >> 5);
    float sy = fmaf((float)(2 * lblk), s, s_hi);
    float sx = fmaf(wt, s, sxl);
    float sz = fmaf(fd, s, szf);

    // warp reduction
    const unsigned FULL = 0xFFFFFFFFu;
#pragma unroll
    for (int off = 16; off > 0; off >>= 1) {
        s  += __shfl_down_sync(FULL, s,  off);
        sy += __shfl_down_sync(FULL, sy, off);
        sx += __shfl_down_sync(FULL, sx, off);
        sz += __shfl_down_sync(FULL, sz, off);
    }

    __shared__ float4 warp_acc[THREADS / 32];
    int lane = tid & 31;
    int wid  = tid >> 5;
    if (lane == 0) warp_acc[wid] = make_float4(s, sy, sx, sz);
    __syncthreads();

    if (wid == 0) {
        float4 a = (lane < THREADS / 32) ? warp_acc[lane] : make_float4(0.f, 0.f, 0.f, 0.f);
#pragma unroll
        for (int off = 4; off > 0; off >>= 1) {
            a.x += __shfl_down_sync(FULL, a.x, off);
            a.y += __shfl_down_sync(FULL, a.y, off);
            a.z += __shfl_down_sync(FULL, a.z, off);
            a.w += __shfl_down_sync(FULL, a.w, off);
        }
        if (lane == 0) g_partial[blockIdx.x] = a;
    }

    // ---- last-block finalize ----
    __threadfence();
    __shared__ bool is_last;
    if (tid == 0) {
        unsigned old = atomicAdd(&g_count, 1u);
        is_last = (old == (unsigned)(NBLOCKS - 1));
        if (is_last) g_count = 0;            // reset for next graph replay
    }
    __syncthreads();
    if (!is_last) return;
    __threadfence();

    __shared__ float4 sh[NBLOCKS];           // 16 KB
    __shared__ float  cent[NSLICE][3];
#pragma unroll
    for (int k = tid; k < NBLOCKS; k += THREADS) {
        const float4* gp = &g_partial[k];
        float4 a;
        a.x = __ldcg(&gp->x); a.y = __ldcg(&gp->y);
        a.z = __ldcg(&gp->z); a.w = __ldcg(&gp->w);
        sh[k] = a;
    }
    __syncthreads();

    if (tid < NSLICE) {
        float ss = 0.f, ssy = 0.f, ssx = 0.f, ssz = 0.f;
#pragma unroll
        for (int k = 0; k < BLK_PER_SL; k++) {
            float4 a = sh[tid * BLK_PER_SL + k];
            ss += a.x; ssy += a.y; ssx += a.z; ssz += a.w;
        }
        const float inv128 = 1.0f / 128.0f;
        float inv_s = 1.0f / ss;             // inf if ss==0; guarded below
        cent[tid][0] = ssy * inv_s * inv128;
        cent[tid][1] = ssx * inv_s * inv128;
        cent[tid][2] = ssz * inv_s * inv128;
    }
    __syncthreads();

    if (tid == 0) {
        float loss = 0.f;
#pragma unroll
        for (int r = 0; r < 8; r++) {
            int i = c_ri[r], j = c_rj[r];
            float acc = 0.f;
#pragma unroll
            for (int b = 0; b < 2; b++) {
                float dy = cent[b * 8 + i][0] - cent[b * 8 + j][0] - c_gy[r];
                float dx = cent[b * 8 + i][1] - cent[b * 8 + j][1] - c_gx[r];
                float dz = cent[b * 8 + i][2] - cent[b * 8 + j][2] - c_gz[r];
                if (!isfinite(dy)) dy = 0.f;
                if (!isfinite(dx)) dx = 0.f;
                if (!isfinite(dz)) dz = 0.f;
                acc += dy * dy + dx * dx + dz * dz;
            }
            loss += 0.5f * acc;              // mean over batch (B=2)
        }
        out[0] = loss;
    }
}

extern "C" void kernel_launch(void* const* d_in, const int* in_sizes, int n_in,
                              void* d_out, int out_size) {
    const float* in = (const float*)d_in[0];
    float* out = (float*)d_out;
    (void)in_sizes; (void)n_in; (void)out_size;

    fused_kernel<<<NBLOCKS, THREADS>>>(in, out);
}

// round 9
// speedup vs baseline: 1.2123x; 1.0519x over previous
#include <cuda_runtime.h>
#include <cuda_bf16.h>
#include <math.h>

// Shape (fixed): output [B=2, C=8, H=128, W=128, D=128] fp32.
// Slice = 128^3 elems = 524,288 float4.
// Grid: 512 blocks x 256 threads, one wave (4 CTA/SM budget -> 64 regs).
// Block = 16384 float4 = 64/thread, as 8 batches of 8 front-batched LDG.128.
//
// Slice-local f4 = lblk*16384 + batch*2048 + u*256 + tid:
//   h = 4*lblk + (batch>>1)               (per-batch constant -> 4 partial sums)
//   w = 64*(batch&1) + 8*u + (tid>>5)     (immediate + hoisted thread part)
//   d = 4*(tid&31) + lane-fraction        (hoisted + t1+2t2+3t3)

#define NSLICE       16
#define BLK_PER_SL   32
#define NBLOCKS      (NSLICE * BLK_PER_SL)   // 512
#define THREADS      256
#define F4_PER_BLK   16384
#define SLICE_F4     524288

__device__ float4 g_partial[NBLOCKS];
__device__ unsigned int g_count = 0;

__device__ __constant__ int   c_ri[8] = {0, 1, 2, 3, 4, 5, 6, 0};
__device__ __constant__ int   c_rj[8] = {1, 2, 3, 4, 5, 6, 7, 7};
__device__ __constant__ float c_gy[8] = { 0.1f, 0.0f, -0.1f, 0.0f,  0.05f, 0.0f,  0.1f, -0.05f};
__device__ __constant__ float c_gx[8] = { 0.0f, 0.1f,  0.05f, 0.0f, -0.05f, 0.1f, 0.0f,  0.05f};
__device__ __constant__ float c_gz[8] = { 0.05f, 0.0f, 0.0f,  0.1f,  0.0f, -0.1f, 0.0f,  0.05f};

__global__ __launch_bounds__(THREADS, 4) void fused_kernel(const float* __restrict__ in,
                                                           float* __restrict__ out) {
    const int bc   = blockIdx.x >> 5;        // slice 0..15
    const int lblk = blockIdx.x & 31;        // block within slice
    const int tid  = threadIdx.x;

    const float4* __restrict__ p =
        reinterpret_cast<const float4*>(in) + (size_t)bc * SLICE_F4 + (size_t)lblk * F4_PER_BLK;

    // h-partials for h = 4*lblk + 0..3, plus w-fraction and d-fraction sums
    float sh0 = 0.f, sh1 = 0.f, sh2 = 0.f, sh3 = 0.f;
    float sxl = 0.f, szf = 0.f;

#pragma unroll
    for (int batch = 0; batch < 8; batch++) {
        // 8 independent LDG.128 front-batched into named registers
        float4 v0 = p[batch * 2048 + 0 * 256 + tid];
        float4 v1 = p[batch * 2048 + 1 * 256 + tid];
        float4 v2 = p[batch * 2048 + 2 * 256 + tid];
        float4 v3 = p[batch * 2048 + 3 * 256 + tid];
        float4 v4 = p[batch * 2048 + 4 * 256 + tid];
        float4 v5 = p[batch * 2048 + 5 * 256 + tid];
        float4 v6 = p[batch * 2048 + 6 * 256 + tid];
        float4 v7 = p[batch * 2048 + 7 * 256 + tid];

        float bsum = 0.f;
#pragma unroll
        for (int u = 0; u < 8; u++) {
            float4 v = (u == 0) ? v0 : (u == 1) ? v1 : (u == 2) ? v2 : (u == 3) ? v3
                     : (u == 4) ? v4 : (u == 5) ? v5 : (u == 6) ? v6 : v7;
            float t0 = v.x > 0.5f ? v.x : 0.f;
            float t1 = v.y > 0.5f ? v.y : 0.f;
            float t2 = v.z > 0.5f ? v.z : 0.f;
            float t3 = v.w > 0.5f ? v.w : 0.f;
            float tsum = (t0 + t1) + (t2 + t3);

            bsum += tsum;
            // w immediate part: 64*(batch&1) + 8*u  -> FFMA with immediate
            sxl = fmaf(tsum, (float)(64 * (batch & 1) + 8 * u), sxl);
            // intra-f4 d fraction: t1 + 2*t2 + 3*t3
            szf += t1;
            szf = fmaf(2.f, t2, szf);
            szf = fmaf(3.f, t3, szf);
        }
        // h = 4*lblk + (batch>>1)
        if      (batch < 2) sh0 += bsum;
        else if (batch < 4) sh1 += bsum;
        else if (batch < 6) sh2 += bsum;
        else                sh3 += bsum;
    }

    float s  = (sh0 + sh1) + (sh2 + sh3);
    float sy = fmaf((float)(4 * lblk), s, sh1 + 2.f * sh2 + 3.f * sh3);
    float sx = fmaf((float)(tid >> 5), s, sxl);
    float sz = fmaf((float)((tid & 31) << 2), s, szf);

    // warp reduction
    const unsigned FULL = 0xFFFFFFFFu;
#pragma unroll
    for (int off = 16; off > 0; off >>= 1) {
        s  += __shfl_down_sync(FULL, s,  off);
        sy += __shfl_down_sync(FULL, sy, off);
        sx += __shfl_down_sync(FULL, sx, off);
        sz += __shfl_down_sync(FULL, sz, off);
    }

    __shared__ float4 warp_acc[THREADS / 32];
    int lane = tid & 31;
    int wid  = tid >> 5;
    if (lane == 0) warp_acc[wid] = make_float4(s, sy, sx, sz);
    __syncthreads();

    if (wid == 0) {
        float4 a = (lane < THREADS / 32) ? warp_acc[lane] : make_float4(0.f, 0.f, 0.f, 0.f);
#pragma unroll
        for (int off = 4; off > 0; off >>= 1) {
            a.x += __shfl_down_sync(FULL, a.x, off);
            a.y += __shfl_down_sync(FULL, a.y, off);
            a.z += __shfl_down_sync(FULL, a.z, off);
            a.w += __shfl_down_sync(FULL, a.w, off);
        }
        if (lane == 0) g_partial[blockIdx.x] = a;
    }

    // ---- last-block finalize (threadfence reduction) ----
    __threadfence();
    __shared__ bool is_last;
    if (tid == 0) {
        unsigned old = atomicAdd(&g_count, 1u);
        is_last = (old == (unsigned)(NBLOCKS - 1));
        if (is_last) g_count = 0;            // reset for next graph replay
    }
    __syncthreads();
    if (!is_last) return;
    __threadfence();

    __shared__ float4 shp[NBLOCKS];          // 8 KB
    __shared__ float  cent[NSLICE][3];
#pragma unroll
    for (int k = tid; k < NBLOCKS; k += THREADS) {
        const float4* gp = &g_partial[k];
        float4 a;
        a.x = __ldcg(&gp->x); a.y = __ldcg(&gp->y);
        a.z = __ldcg(&gp->z); a.w = __ldcg(&gp->w);
        shp[k] = a;
    }
    __syncthreads();

    if (tid < NSLICE) {
        float ss = 0.f, ssy = 0.f, ssx = 0.f, ssz = 0.f;
#pragma unroll
        for (int k = 0; k < BLK_PER_SL; k++) {
            float4 a = shp[tid * BLK_PER_SL + k];
            ss += a.x; ssy += a.y; ssx += a.z; ssz += a.w;
        }
        const float inv128 = 1.0f / 128.0f;
        float inv_s = 1.0f / ss;             // inf if ss==0; guarded below
        cent[tid][0] = ssy * inv_s * inv128;
        cent[tid][1] = ssx * inv_s * inv128;
        cent[tid][2] = ssz * inv_s * inv128;
    }
    __syncthreads();

    if (tid == 0) {
        float loss = 0.f;
#pragma unroll
        for (int r = 0; r < 8; r++) {
            int i = c_ri[r], j = c_rj[r];
            float acc = 0.f;
#pragma unroll
            for (int b = 0; b < 2; b++) {
                float dy = cent[b * 8 + i][0] - cent[b * 8 + j][0] - c_gy[r];
                float dx = cent[b * 8 + i][1] - cent[b * 8 + j][1] - c_gx[r];
                float dz = cent[b * 8 + i][2] - cent[b * 8 + j][2] - c_gz[r];
                if (!isfinite(dy)) dy = 0.f;
                if (!isfinite(dx)) dx = 0.f;
                if (!isfinite(dz)) dz = 0.f;
                acc += dy * dy + dx * dx + dz * dz;
            }
            loss += 0.5f * acc;              // mean over batch (B=2)
        }
        out[0] = loss;
    }
}

extern "C" void kernel_launch(void* const* d_in, const int* in_sizes, int n_in,
                              void* d_out, int out_size) {
    const float* in = (const float*)d_in[0];
    float* out = (float*)d_out;
    (void)in_sizes; (void)n_in; (void)out_size;

    fused_kernel<<<NBLOCKS, THREADS>>>(in, out);
}